// round 1
// baseline (speedup 1.0000x reference)
#include <cuda_runtime.h>
#include <cuda_bf16.h>

// Perceive3D: out[b, k*16+c, z, h, w] for k in {ident, sobel_x(W-deriv), sobel_y(H-deriv), sobel_z(D-deriv)}
// Kernels are separable: s=[1,2,1], d=[-1,0,1], all /16. Replicate (edge) padding.
//
// Strategy: one block per (channel, H-tile of 8). Block = (64,8) threads = full W line x 8 rows.
// Slide along D (z). Per z-plane: cooperative SMEM load of (10 x 66) halo'd plane (edge-clamped),
// then each thread reduces its 3x3 neighborhood to 4 scalars:
//   P  = sum s(dy)s(dx) a   (smooth HxW)        -> D-derivative uses P[z+1]-P[z-1]
//   QW = sum s(dy)d(dx) a   (W-deriv, H-smooth) -> sx = QW[z-1]+2QW[z]+QW[z+1]
//   QH = sum d(dy)s(dx) a                       -> sy = QH[z-1]+2QH[z]+QH[z+1]
//   CC = center sample                          -> identity = CC[z]
// 3-deep register rotation over z; SMEM double-buffered (1 barrier per z step).

#define W64 64
#define HT  8
#define PW  66   // 64 + 2 halo
#define PH  10   // 8 + 2 halo

__global__ __launch_bounds__(512, 2)
void perceive3d_kernel(const float* __restrict__ x, float* __restrict__ out) {
    __shared__ float plane[2][PH * PW];

    const int lx  = threadIdx.x;            // 0..63 (W)
    const int ly  = threadIdx.y;            // 0..7  (H within tile)
    const int tid = ly * W64 + lx;          // 0..511
    const int h0  = blockIdx.x * HT;        // H tile base
    const int bc  = blockIdx.y;             // 0..63 = b*16 + c
    const int b   = bc >> 4;
    const int c   = bc & 15;

    const size_t cstride = (size_t)64 * 64 * 64;           // one channel volume
    const float* __restrict__ xin = x + (size_t)bc * cstride;
    float* __restrict__ out0 = out + ((size_t)(b * 64) + c) * cstride;  // k=0 channel base

    const int h    = h0 + ly;
    const int line = h * 64 + lx;

    float P[3], QW[3], QH[3], CC[3];

    // ---- cooperative halo'd plane load with edge clamping ----
    auto loadPlane = [&](int z, int which) {
        int zz = z < 0 ? 0 : (z > 63 ? 63 : z);
        const float* __restrict__ src = xin + (size_t)zz * 4096;
        #pragma unroll
        for (int i = tid; i < PH * PW; i += 512) {
            int row = i / PW;
            int col = i - row * PW;
            int gy = h0 + row - 1; gy = gy < 0 ? 0 : (gy > 63 ? 63 : gy);
            int gx = col - 1;      gx = gx < 0 ? 0 : (gx > 63 ? 63 : gx);
            plane[which][i] = src[gy * 64 + gx];
        }
    };

    // ---- per-thread 3x3 reduction of a plane into (P, QW, QH, CC) ----
    auto computeStats = [&](int which, int slot) {
        const float* __restrict__ p = plane[which];
        float sw0, sw1, sw2, dw0, dw1, dw2;
        {
            float r0 = p[(ly + 0) * PW + lx + 0];
            float r1 = p[(ly + 0) * PW + lx + 1];
            float r2 = p[(ly + 0) * PW + lx + 2];
            sw0 = r0 + 2.f * r1 + r2;  dw0 = r2 - r0;
        }
        {
            float r0 = p[(ly + 1) * PW + lx + 0];
            float r1 = p[(ly + 1) * PW + lx + 1];
            float r2 = p[(ly + 1) * PW + lx + 2];
            sw1 = r0 + 2.f * r1 + r2;  dw1 = r2 - r0;
            CC[slot] = r1;
        }
        {
            float r0 = p[(ly + 2) * PW + lx + 0];
            float r1 = p[(ly + 2) * PW + lx + 1];
            float r2 = p[(ly + 2) * PW + lx + 2];
            sw2 = r0 + 2.f * r1 + r2;  dw2 = r2 - r0;
        }
        P [slot] = sw0 + 2.f * sw1 + sw2;
        QW[slot] = dw0 + 2.f * dw1 + dw2;
        QH[slot] = sw2 - sw0;
    };

    // ---- prologue: planes z=-1 (slot 0) and z=0 (slot 1) ----
    loadPlane(-1, 0);
    __syncthreads();
    computeStats(0, 0);

    loadPlane(0, 1);
    __syncthreads();
    computeStats(1, 1);

    int buf = 0;
    #pragma unroll 3
    for (int z = 0; z < 64; z++) {
        // load plane z+1 into `buf`; safe: buf's previous contents were consumed
        // before the barrier of the previous iteration.
        loadPlane(z + 1, buf);
        __syncthreads();

        const int sNew  = (z + 2) % 3;  // z+1
        const int sCur  = (z + 1) % 3;  // z
        const int sPrev =  z      % 3;  // z-1
        computeStats(buf, sNew);
        buf ^= 1;

        const float ident = CC[sCur];
        const float sx = (QW[sPrev] + 2.f * QW[sCur] + QW[sNew]) * 0.0625f;
        const float sy = (QH[sPrev] + 2.f * QH[sCur] + QH[sNew]) * 0.0625f;
        const float sz = (P[sNew] - P[sPrev]) * 0.0625f;

        const size_t o = (size_t)z * 4096 + line;
        out0[o                 ] = ident;
        out0[o + 16 * cstride  ] = sx;
        out0[o + 32 * cstride  ] = sy;
        out0[o + 48 * cstride  ] = sz;
    }
}

extern "C" void kernel_launch(void* const* d_in, const int* in_sizes, int n_in,
                              void* d_out, int out_size) {
    const float* x = (const float*)d_in[0];
    // d_in[1] = kernels (3x3x3 x4) — fixed separable stencils, folded into the kernel.
    float* out = (float*)d_out;

    dim3 grid(64 / HT, 64);   // (H tiles, B*C channels)
    dim3 block(W64, HT);      // 512 threads
    perceive3d_kernel<<<grid, block>>>(x, out);
}

// round 2
// speedup vs baseline: 1.6391x; 1.6391x over previous
#include <cuda_runtime.h>
#include <cuda_bf16.h>
#include <cstdint>

// Perceive3D: out[b, k*16+c, z, h, w], k in {identity, d/dW, d/dH, d/dD} (Sobel-smoothed, /16),
// replicate padding. Separable: s=[1,2,1], d=[-1,0,1].
//
// R2: cp.async pipelined plane loader (ring of 4 SMEM buffers, prefetch depth 2),
// 256-thread blocks (64x4 tile) for 5 CTAs/SM, 16B vector async loads for the
// row interiors + 4B async loads for the 2 edge-clamped halo columns.

#define HT   4         // H rows per block
#define PW   72        // padded plane row: [3]=left halo, [4..67]=interior, [68]=right halo
#define PH   6         // HT + 2 halo rows
#define NB   4         // plane ring buffers

__device__ __forceinline__ uint32_t smem_u32(const void* p) {
    uint32_t a;
    asm("{ .reg .u64 t; cvta.to.shared.u64 t, %1; cvt.u32.u64 %0, t; }" : "=r"(a) : "l"(p));
    return a;
}
__device__ __forceinline__ void cp_async16(uint32_t s, const void* g) {
    asm volatile("cp.async.cg.shared.global [%0], [%1], 16;" :: "r"(s), "l"(g));
}
__device__ __forceinline__ void cp_async4(uint32_t s, const void* g) {
    asm volatile("cp.async.ca.shared.global [%0], [%1], 4;" :: "r"(s), "l"(g));
}
__device__ __forceinline__ void cp_commit() {
    asm volatile("cp.async.commit_group;");
}
template <int N>
__device__ __forceinline__ void cp_wait() {
    asm volatile("cp.async.wait_group %0;" :: "n"(N));
}

__global__ __launch_bounds__(256, 5)
void perceive3d_kernel(const float* __restrict__ x, float* __restrict__ out) {
    __shared__ float plane[NB][PH * PW];

    const int lx  = threadIdx.x;           // 0..63 (W)
    const int ly  = threadIdx.y;           // 0..3  (H in tile)
    const int tid = ly * 64 + lx;          // 0..255
    const int h0  = blockIdx.x * HT;
    const int bc  = blockIdx.y;            // 0..63 = b*16+c
    const int b   = bc >> 4;
    const int c   = bc & 15;

    const size_t cstride = (size_t)64 * 64 * 64;
    const float* __restrict__ xin = x + (size_t)bc * cstride;
    float* __restrict__ out0 = out + ((size_t)(b * 64) + c) * cstride;

    const int line = (h0 + ly) * 64 + lx;

    // precompute this thread's load slot (same for every plane)
    //   tid 0..95  : vector op, row = tid>>4 (0..5), j = tid&15 -> 16B at cols [4+4j .. 7+4j]
    //   tid 96..107: scalar halo op, row = (tid-96)>>1, side = (tid-96)&1
    int ld_row = -1, ld_j = 0, ld_side = 0;
    bool ld_vec = false, ld_sca = false;
    if (tid < 96)       { ld_vec = true; ld_row = tid >> 4;        ld_j = tid & 15; }
    else if (tid < 108) { ld_sca = true; ld_row = (tid - 96) >> 1; ld_side = (tid - 96) & 1; }
    int gy = h0 + ld_row - 1;
    gy = gy < 0 ? 0 : (gy > 63 ? 63 : gy);
    const uint32_t smem_vec = ld_vec ? smem_u32(&plane[0][ld_row * PW + 4 + 4 * ld_j]) : 0;
    const uint32_t smem_sca = ld_sca ? smem_u32(&plane[0][ld_row * PW + (ld_side ? 68 : 3)]) : 0;
    const int      goff_vec = gy * 64 + 4 * ld_j;
    const int      goff_sca = gy * 64 + (ld_side ? 63 : 0);
    const uint32_t bufBytes = PH * PW * 4;

    auto loadPlane = [&](int z, int buf) {
        int zz = z < 0 ? 0 : (z > 63 ? 63 : z);
        const float* __restrict__ src = xin + (size_t)zz * 4096;
        if (ld_vec)      cp_async16(smem_vec + buf * bufBytes, src + goff_vec);
        else if (ld_sca) cp_async4 (smem_sca + buf * bufBytes, src + goff_sca);
        cp_commit();
    };

    // per-thread 3x3 reduction of a plane -> (P = ss smooth, QW = sd, QH = ds, CC = center)
    auto stats = [&](int buf, float& P, float& QW, float& QH, float& CC) {
        const float* __restrict__ p = plane[buf] + ly * PW + lx + 3;
        float r0 = p[0],            r1 = p[1],            r2 = p[2];
        float sw0 = r0 + 2.f * r1 + r2, dw0 = r2 - r0;
        r0 = p[PW];  r1 = p[PW + 1];  r2 = p[PW + 2];
        float sw1 = r0 + 2.f * r1 + r2, dw1 = r2 - r0;
        CC = r1;
        r0 = p[2 * PW];  r1 = p[2 * PW + 1];  r2 = p[2 * PW + 2];
        float sw2 = r0 + 2.f * r1 + r2, dw2 = r2 - r0;
        P  = sw0 + 2.f * sw1 + sw2;
        QW = dw0 + 2.f * dw1 + dw2;
        QH = sw2 - sw0;
    };

    float Pp, Pc, Pn, Wp, Wc, Wn, Hp, Hc, Hn, Cc, Cn, Cd;

    // prologue: planes -1, 0, 1 into bufs 0,1,2 (plane p -> buf (p+1)&3)
    loadPlane(-1, 0);
    loadPlane( 0, 1);
    loadPlane( 1, 2);
    cp_wait<1>();          // planes -1, 0 complete
    __syncthreads();
    stats(0, Pp, Wp, Hp, Cd);
    stats(1, Pc, Wc, Hc, Cc);

    #pragma unroll 4
    for (int z = 0; z < 64; z++) {
        // prefetch plane z+2 into buf (z+3)&3 (held plane z-2; reads finished iters ago)
        loadPlane(z + 2, (z + 3) & 3);
        cp_wait<1>();      // plane z+1 complete (z+2 may still be in flight)
        __syncthreads();

        stats((z + 2) & 3, Pn, Wn, Hn, Cn);

        const float sx = (Wp + 2.f * Wc + Wn) * 0.0625f;
        const float sy = (Hp + 2.f * Hc + Hn) * 0.0625f;
        const float sz = (Pn - Pp) * 0.0625f;

        const size_t o = (size_t)z * 4096 + line;
        __stcs(out0 + o,                Cc);
        __stcs(out0 + o + 16 * cstride, sx);
        __stcs(out0 + o + 32 * cstride, sy);
        __stcs(out0 + o + 48 * cstride, sz);

        Pp = Pc; Pc = Pn;
        Wp = Wc; Wc = Wn;
        Hp = Hc; Hc = Hn;
        Cc = Cn;

        // barrier before next iteration's prefetch may overwrite a buffer that
        // other threads are still reading in stats() above
        __syncthreads();
    }
}

extern "C" void kernel_launch(void* const* d_in, const int* in_sizes, int n_in,
                              void* d_out, int out_size) {
    const float* x = (const float*)d_in[0];
    // d_in[1] = kernels (4x3x3x3) — fixed separable stencils folded into the kernel.
    float* out = (float*)d_out;

    dim3 grid(64 / HT, 64);   // (H tiles, B*C)
    dim3 block(64, HT);       // 256 threads
    perceive3d_kernel<<<grid, block>>>(x, out);
}

// round 3
// speedup vs baseline: 1.9595x; 1.1955x over previous
#include <cuda_runtime.h>
#include <cuda_bf16.h>
#include <cstdint>

// Perceive3D: out[b, k*16+c, z, h, w], k in {identity, d/dW, d/dH, d/dD} (Sobel-smoothed, /16),
// replicate padding. Separable: s=[1,2,1], d=[-1,0,1].
//
// R3: deep cp.async pipeline — ring of 6 SMEM plane buffers, prefetch distance 3
// (plane z+4 issued at iter z, wait_group<=3 guarantees plane z+1), and a single
// __syncthreads per z-iteration (ring depth makes the WAR window 3 iterations,
// warp skew bounded to 1 by the per-iter barrier).

#define HT   4         // H rows per block
#define PW   72        // padded row: [3]=left halo, [4..67]=interior, [68]=right halo
#define PH   6         // HT + 2 halo rows
#define NB   6         // plane ring buffers

__device__ __forceinline__ uint32_t smem_u32(const void* p) {
    uint32_t a;
    asm("{ .reg .u64 t; cvta.to.shared.u64 t, %1; cvt.u32.u64 %0, t; }" : "=r"(a) : "l"(p));
    return a;
}
__device__ __forceinline__ void cp_async16(uint32_t s, const void* g) {
    asm volatile("cp.async.cg.shared.global [%0], [%1], 16;" :: "r"(s), "l"(g));
}
__device__ __forceinline__ void cp_async4(uint32_t s, const void* g) {
    asm volatile("cp.async.ca.shared.global [%0], [%1], 4;" :: "r"(s), "l"(g));
}
__device__ __forceinline__ void cp_commit() {
    asm volatile("cp.async.commit_group;");
}
template <int N>
__device__ __forceinline__ void cp_wait() {
    asm volatile("cp.async.wait_group %0;" :: "n"(N));
}

__global__ __launch_bounds__(256, 5)
void perceive3d_kernel(const float* __restrict__ x, float* __restrict__ out) {
    __shared__ float plane[NB][PH * PW];

    const int lx  = threadIdx.x;           // 0..63 (W)
    const int ly  = threadIdx.y;           // 0..3  (H in tile)
    const int tid = ly * 64 + lx;          // 0..255
    const int h0  = blockIdx.x * HT;
    const int bc  = blockIdx.y;            // 0..63 = b*16+c
    const int b   = bc >> 4;
    const int c   = bc & 15;

    const size_t cstride = (size_t)64 * 64 * 64;
    const float* __restrict__ xin = x + (size_t)bc * cstride;
    float* __restrict__ out0 = out + ((size_t)(b * 64) + c) * cstride;

    const int line = (h0 + ly) * 64 + lx;

    // per-thread load slot (same for every plane):
    //   tid 0..95  : 16B vector op, row = tid>>4 (0..5), j = tid&15 -> cols [4j .. 4j+3]
    //   tid 96..107: 4B halo op,   row = (tid-96)>>1, side = (tid-96)&1
    int ld_row = 0, ld_j = 0, ld_side = 0;
    bool ld_vec = false, ld_sca = false;
    if (tid < 96)       { ld_vec = true; ld_row = tid >> 4;        ld_j = tid & 15; }
    else if (tid < 108) { ld_sca = true; ld_row = (tid - 96) >> 1; ld_side = (tid - 96) & 1; }
    int gy = h0 + ld_row - 1;
    gy = gy < 0 ? 0 : (gy > 63 ? 63 : gy);
    const uint32_t smem_vec = ld_vec ? smem_u32(&plane[0][ld_row * PW + 4 + 4 * ld_j]) : 0;
    const uint32_t smem_sca = ld_sca ? smem_u32(&plane[0][ld_row * PW + (ld_side ? 68 : 3)]) : 0;
    const int      goff_vec = gy * 64 + 4 * ld_j;
    const int      goff_sca = gy * 64 + (ld_side ? 63 : 0);
    const uint32_t bufBytes = PH * PW * 4;

    // plane p lives in buf (p+1) % 6
    auto loadPlane = [&](int z, int buf) {
        int zz = z < 0 ? 0 : (z > 63 ? 63 : z);
        const float* __restrict__ src = xin + (size_t)zz * 4096;
        if (ld_vec)      cp_async16(smem_vec + buf * bufBytes, src + goff_vec);
        else if (ld_sca) cp_async4 (smem_sca + buf * bufBytes, src + goff_sca);
        cp_commit();
    };

    // per-thread 3x3 reduction -> (P = s⊗s, QW = s⊗d, QH = d⊗s, CC = center)
    auto stats = [&](int buf, float& P, float& QW, float& QH, float& CC) {
        const float* __restrict__ p = plane[buf] + ly * PW + lx + 3;
        float r0 = p[0],            r1 = p[1],            r2 = p[2];
        float sw0 = r0 + 2.f * r1 + r2, dw0 = r2 - r0;
        r0 = p[PW];  r1 = p[PW + 1];  r2 = p[PW + 2];
        float sw1 = r0 + 2.f * r1 + r2, dw1 = r2 - r0;
        CC = r1;
        r0 = p[2 * PW];  r1 = p[2 * PW + 1];  r2 = p[2 * PW + 2];
        float sw2 = r0 + 2.f * r1 + r2, dw2 = r2 - r0;
        P  = sw0 + 2.f * sw1 + sw2;
        QW = dw0 + 2.f * dw1 + dw2;
        QH = sw2 - sw0;
    };

    float Pp, Pc, Pn, Wp, Wc, Wn, Hp, Hc, Hn, Cc, Cn, Cd;

    // prologue: planes -1..3 into bufs 0..4 (one commit group each)
    loadPlane(-1, 0);
    loadPlane( 0, 1);
    loadPlane( 1, 2);
    loadPlane( 2, 3);
    loadPlane( 3, 4);
    cp_wait<3>();          // planes -1, 0 complete (<=3 of 5 groups pending)
    __syncthreads();
    stats(0, Pp, Wp, Hp, Cd);
    stats(1, Pc, Wc, Hc, Cc);

    #pragma unroll 2
    for (int z = 0; z < 64; z++) {
        // prefetch plane z+4 into buf (z+5)%6 — that buffer held plane z-2,
        // last read by stats at iter z-3; per-iter barrier bounds warp skew to 1,
        // so barriers at iters z-2 and z-1 make the overwrite safe.
        loadPlane(z + 4, (z + 5) % 6);
        cp_wait<3>();      // plane z+1 complete (z+2..z+4 may be in flight)
        __syncthreads();

        stats((z + 2) % 6, Pn, Wn, Hn, Cn);

        const float sx = (Wp + 2.f * Wc + Wn) * 0.0625f;
        const float sy = (Hp + 2.f * Hc + Hn) * 0.0625f;
        const float sz = (Pn - Pp) * 0.0625f;

        const size_t o = (size_t)z * 4096 + line;
        __stcs(out0 + o,                Cc);
        __stcs(out0 + o + 16 * cstride, sx);
        __stcs(out0 + o + 32 * cstride, sy);
        __stcs(out0 + o + 48 * cstride, sz);

        Pp = Pc; Pc = Pn;
        Wp = Wc; Wc = Wn;
        Hp = Hc; Hc = Hn;
        Cc = Cn;
    }
}

extern "C" void kernel_launch(void* const* d_in, const int* in_sizes, int n_in,
                              void* d_out, int out_size) {
    const float* x = (const float*)d_in[0];
    // d_in[1] = kernels (4x3x3x3) — fixed separable stencils folded into the kernel.
    float* out = (float*)d_out;

    dim3 grid(64 / HT, 64);   // (H tiles, B*C)
    dim3 block(64, HT);       // 256 threads
    perceive3d_kernel<<<grid, block>>>(x, out);
}

// round 4
// speedup vs baseline: 1.9783x; 1.0096x over previous
#include <cuda_runtime.h>
#include <cuda_bf16.h>
#include <cstdint>

// Perceive3D: out[b, k*16+c, z, h, w], k in {identity, d/dW, d/dH, d/dD} (Sobel-smoothed, /16),
// replicate padding. Separable: s=[1,2,1], d=[-1,0,1].
//
// R4: 128-thread blocks (32x4), each thread computes 2 adjacent W voxels (float2 loads/stores),
// ring of 8 SMEM plane buffers (&7 indexing, no modulo), prefetch distance 3,
// single wave: 1024 blocks @ 8 CTAs/SM = 1184 slots (1.2% imbalance).

#define HT   4         // H rows per block
#define PW   72        // [3]=left halo, [4..67]=interior (16B aligned), [68]=right halo
#define PH   6         // HT + 2 halo rows
#define NB   8         // plane ring buffers (plane p -> buf (p+1)&7)

__device__ __forceinline__ uint32_t smem_u32(const void* p) {
    uint32_t a;
    asm("{ .reg .u64 t; cvta.to.shared.u64 t, %1; cvt.u32.u64 %0, t; }" : "=r"(a) : "l"(p));
    return a;
}
__device__ __forceinline__ void cp_async16(uint32_t s, const void* g) {
    asm volatile("cp.async.cg.shared.global [%0], [%1], 16;" :: "r"(s), "l"(g));
}
__device__ __forceinline__ void cp_async4(uint32_t s, const void* g) {
    asm volatile("cp.async.ca.shared.global [%0], [%1], 4;" :: "r"(s), "l"(g));
}
__device__ __forceinline__ void cp_commit() {
    asm volatile("cp.async.commit_group;");
}
template <int N>
__device__ __forceinline__ void cp_wait() {
    asm volatile("cp.async.wait_group %0;" :: "n"(N));
}

__global__ __launch_bounds__(128, 8)
void perceive3d_kernel(const float* __restrict__ x, float* __restrict__ out) {
    __shared__ float plane[NB][PH * PW];

    const int lx  = threadIdx.x;           // 0..31 -> W pair (2*lx, 2*lx+1)
    const int ly  = threadIdx.y;           // 0..3  (H in tile)
    const int tid = ly * 32 + lx;          // 0..127
    const int h0  = blockIdx.x * HT;
    const int bc  = blockIdx.y;            // 0..63 = b*16+c
    const int b   = bc >> 4;
    const int c   = bc & 15;

    const size_t cstride = (size_t)64 * 64 * 64;
    const float* __restrict__ xin = x + (size_t)bc * cstride;
    float* __restrict__ out0 = out + ((size_t)(b * 64) + c) * cstride;

    const int line = (h0 + ly) * 64 + 2 * lx;

    // per-thread load slot (fixed across planes):
    //   tid 0..95  : 16B vector op, row = tid>>4 (0..5), j = tid&15 -> input cols [4j..4j+3]
    //   tid 96..107: 4B halo op,    row = (tid-96)>>1, side = (tid-96)&1
    int ld_row = 0, ld_j = 0, ld_side = 0;
    bool ld_vec = false, ld_sca = false;
    if (tid < 96)       { ld_vec = true; ld_row = tid >> 4;        ld_j = tid & 15; }
    else if (tid < 108) { ld_sca = true; ld_row = (tid - 96) >> 1; ld_side = (tid - 96) & 1; }
    int gy = h0 + ld_row - 1;
    gy = gy < 0 ? 0 : (gy > 63 ? 63 : gy);
    const uint32_t smem_vec = ld_vec ? smem_u32(&plane[0][ld_row * PW + 4 + 4 * ld_j]) : 0;
    const uint32_t smem_sca = ld_sca ? smem_u32(&plane[0][ld_row * PW + (ld_side ? 68 : 3)]) : 0;
    const int      goff_vec = gy * 64 + 4 * ld_j;
    const int      goff_sca = gy * 64 + (ld_side ? 63 : 0);
    const uint32_t bufBytes = PH * PW * 4;

    auto loadPlane = [&](int z, int buf) {
        int zz = z < 0 ? 0 : (z > 63 ? 63 : z);
        const float* __restrict__ src = xin + (size_t)zz * 4096;
        if (ld_vec)      cp_async16(smem_vec + buf * bufBytes, src + goff_vec);
        else if (ld_sca) cp_async4 (smem_sca + buf * bufBytes, src + goff_sca);
        cp_commit();
    };

    // per-thread 3x3 reduction for a W-pair -> P (s⊗s), QW (s⊗d), QH (d⊗s), CC, each float2.
    // Needed input cols for pair (2lx, 2lx+1): 2lx-1 .. 2lx+2 = smem idx 3+2lx .. 6+2lx.
    // Load 3 float2s at even idx 2+2lx, 4+2lx, 6+2lx (8B aligned); a1..a4 = idx 3..6 (+2lx).
    auto stats = [&](int buf, float2& P, float2& QW, float2& QH, float2& CC) {
        const float* __restrict__ p = plane[buf] + ly * PW + 2 * lx;
        float sw0a, sw0b, dw0a, dw0b;
        float sw1a, sw1b, dw1a, dw1b;
        float sw2a, sw2b, dw2a, dw2b;
        {
            float2 e0 = *(const float2*)(p + 2);
            float2 e1 = *(const float2*)(p + 4);
            float2 e2 = *(const float2*)(p + 6);
            float a1 = e0.y, a2 = e1.x, a3 = e1.y, a4 = e2.x;
            sw0a = a1 + 2.f * a2 + a3;  dw0a = a3 - a1;
            sw0b = a2 + 2.f * a3 + a4;  dw0b = a4 - a2;
        }
        {
            float2 e0 = *(const float2*)(p + PW + 2);
            float2 e1 = *(const float2*)(p + PW + 4);
            float2 e2 = *(const float2*)(p + PW + 6);
            float a1 = e0.y, a2 = e1.x, a3 = e1.y, a4 = e2.x;
            sw1a = a1 + 2.f * a2 + a3;  dw1a = a3 - a1;
            sw1b = a2 + 2.f * a3 + a4;  dw1b = a4 - a2;
            CC.x = a2; CC.y = a3;
        }
        {
            float2 e0 = *(const float2*)(p + 2 * PW + 2);
            float2 e1 = *(const float2*)(p + 2 * PW + 4);
            float2 e2 = *(const float2*)(p + 2 * PW + 6);
            float a1 = e0.y, a2 = e1.x, a3 = e1.y, a4 = e2.x;
            sw2a = a1 + 2.f * a2 + a3;  dw2a = a3 - a1;
            sw2b = a2 + 2.f * a3 + a4;  dw2b = a4 - a2;
        }
        P.x  = sw0a + 2.f * sw1a + sw2a;  P.y  = sw0b + 2.f * sw1b + sw2b;
        QW.x = dw0a + 2.f * dw1a + dw2a;  QW.y = dw0b + 2.f * dw1b + dw2b;
        QH.x = sw2a - sw0a;               QH.y = sw2b - sw0b;
    };

    float2 Pp, Pc, Pn, Wp, Wc, Wn, Hp, Hc, Hn, Cc, Cn, Cd;

    // prologue: planes -1..3 into bufs 0..4 (one commit group each)
    loadPlane(-1, 0);
    loadPlane( 0, 1);
    loadPlane( 1, 2);
    loadPlane( 2, 3);
    loadPlane( 3, 4);
    cp_wait<3>();          // planes -1, 0 complete
    __syncthreads();
    stats(0, Pp, Wp, Hp, Cd);
    stats(1, Pc, Wc, Hc, Cc);

    #pragma unroll 4
    for (int z = 0; z < 64; z++) {
        // prefetch plane z+4 into buf (z+5)&7 — that buffer held plane z-4,
        // last read at iter z-5; per-iter barriers make the overwrite safe.
        loadPlane(z + 4, (z + 5) & 7);
        cp_wait<3>();      // plane z+1 complete (z+2..z+4 in flight)
        __syncthreads();

        stats((z + 2) & 7, Pn, Wn, Hn, Cn);

        float2 sx, sy, sz;
        sx.x = (Wp.x + 2.f * Wc.x + Wn.x) * 0.0625f;
        sx.y = (Wp.y + 2.f * Wc.y + Wn.y) * 0.0625f;
        sy.x = (Hp.x + 2.f * Hc.x + Hn.x) * 0.0625f;
        sy.y = (Hp.y + 2.f * Hc.y + Hn.y) * 0.0625f;
        sz.x = (Pn.x - Pp.x) * 0.0625f;
        sz.y = (Pn.y - Pp.y) * 0.0625f;

        const size_t o = (size_t)z * 4096 + line;
        __stcs((float2*)(out0 + o),                Cc);
        __stcs((float2*)(out0 + o + 16 * cstride), sx);
        __stcs((float2*)(out0 + o + 32 * cstride), sy);
        __stcs((float2*)(out0 + o + 48 * cstride), sz);

        Pp = Pc; Pc = Pn;
        Wp = Wc; Wc = Wn;
        Hp = Hc; Hc = Hn;
        Cc = Cn;
    }
}

extern "C" void kernel_launch(void* const* d_in, const int* in_sizes, int n_in,
                              void* d_out, int out_size) {
    const float* x = (const float*)d_in[0];
    // d_in[1] = kernels (4x3x3x3) — fixed separable stencils folded into the kernel.
    float* out = (float*)d_out;

    dim3 grid(64 / HT, 64);   // (16 H tiles, B*C=64) = 1024 blocks, single wave @ 8 CTA/SM
    dim3 block(32, HT);       // 128 threads
    perceive3d_kernel<<<grid, block>>>(x, out);
}

// round 5
// speedup vs baseline: 2.1676x; 1.0957x over previous
#include <cuda_runtime.h>
#include <cuda_bf16.h>
#include <cstdint>

// Perceive3D: out[b, k*16+c, z, h, w], k in {identity, d/dW, d/dH, d/dD} (Sobel-smoothed, /16),
// replicate padding. Separable: s=[1,2,1], d=[-1,0,1].
//
// R5: 256-thread blocks (32x8, HT=8), 2-wide W voxels per thread, z-split x4
// (16 planes per block -> 2048 blocks = 2.77 waves @ 5 CTA/SM, 8% tail vs 38%),
// ring of 8 SMEM plane buffers, prefetch distance 3, empty commit_groups past range.

#define HT    8        // H rows per block
#define PW    72       // [3]=left halo, [4..67]=interior (16B aligned), [68]=right halo
#define PH    10       // HT + 2 halo rows
#define NB    8        // plane ring buffers
#define ZLEN  16       // z planes per block

__device__ __forceinline__ uint32_t smem_u32(const void* p) {
    uint32_t a;
    asm("{ .reg .u64 t; cvta.to.shared.u64 t, %1; cvt.u32.u64 %0, t; }" : "=r"(a) : "l"(p));
    return a;
}
__device__ __forceinline__ void cp_async16(uint32_t s, const void* g) {
    asm volatile("cp.async.cg.shared.global [%0], [%1], 16;" :: "r"(s), "l"(g));
}
__device__ __forceinline__ void cp_async4(uint32_t s, const void* g) {
    asm volatile("cp.async.ca.shared.global [%0], [%1], 4;" :: "r"(s), "l"(g));
}
__device__ __forceinline__ void cp_commit() {
    asm volatile("cp.async.commit_group;");
}
template <int N>
__device__ __forceinline__ void cp_wait() {
    asm volatile("cp.async.wait_group %0;" :: "n"(N));
}

__global__ __launch_bounds__(256, 5)
void perceive3d_kernel(const float* __restrict__ x, float* __restrict__ out) {
    __shared__ float plane[NB][PH * PW];

    const int lx  = threadIdx.x;           // 0..31 -> W pair (2lx, 2lx+1)
    const int ly  = threadIdx.y;           // 0..7  (H in tile)
    const int tid = ly * 32 + lx;          // 0..255
    const int h0  = blockIdx.x * HT;
    const int bc  = blockIdx.y;            // 0..63 = b*16+c
    const int z0  = blockIdx.z * ZLEN;
    const int b   = bc >> 4;
    const int c   = bc & 15;

    const size_t cstride = (size_t)64 * 64 * 64;
    const float* __restrict__ xin = x + (size_t)bc * cstride;
    float* __restrict__ out0 = out + ((size_t)(b * 64) + c) * cstride;

    const int line = (h0 + ly) * 64 + 2 * lx;

    // per-thread load slot (fixed across planes):
    //   tid 0..159 : 16B vector op, row = tid>>4 (0..9), j = tid&15 -> input cols [4j..4j+3]
    //   tid 160..179: 4B halo op,   row = (tid-160)>>1, side = (tid-160)&1
    int ld_row = 0, ld_j = 0, ld_side = 0;
    bool ld_vec = false, ld_sca = false;
    if (tid < 160)      { ld_vec = true; ld_row = tid >> 4;         ld_j = tid & 15; }
    else if (tid < 180) { ld_sca = true; ld_row = (tid - 160) >> 1; ld_side = (tid - 160) & 1; }
    int gy = h0 + ld_row - 1;
    gy = gy < 0 ? 0 : (gy > 63 ? 63 : gy);
    const uint32_t smem_vec = ld_vec ? smem_u32(&plane[0][ld_row * PW + 4 + 4 * ld_j]) : 0;
    const uint32_t smem_sca = ld_sca ? smem_u32(&plane[0][ld_row * PW + (ld_side ? 68 : 3)]) : 0;
    const int      goff_vec = gy * 64 + 4 * ld_j;
    const int      goff_sca = gy * 64 + (ld_side ? 63 : 0);
    const uint32_t bufBytes = PH * PW * 4;

    // plane with relative index q (= z - z0) lives in buf (q+1)&7
    auto loadPlane = [&](bool go, int z, int buf) {
        if (go) {
            int zz = z < 0 ? 0 : (z > 63 ? 63 : z);
            const float* __restrict__ src = xin + (size_t)zz * 4096;
            if (ld_vec)      cp_async16(smem_vec + buf * bufBytes, src + goff_vec);
            else if (ld_sca) cp_async4 (smem_sca + buf * bufBytes, src + goff_sca);
        }
        cp_commit();
    };

    // per-thread 3x3 reduction for a W-pair -> P (s⊗s), QW (s⊗d), QH (d⊗s), CC, each float2.
    auto stats = [&](int buf, float2& P, float2& QW, float2& QH, float2& CC) {
        const float* __restrict__ p = plane[buf] + ly * PW + 2 * lx;
        float sw0a, sw0b, dw0a, dw0b;
        float sw1a, sw1b, dw1a, dw1b;
        float sw2a, sw2b, dw2a, dw2b;
        {
            float2 e0 = *(const float2*)(p + 2);
            float2 e1 = *(const float2*)(p + 4);
            float2 e2 = *(const float2*)(p + 6);
            float a1 = e0.y, a2 = e1.x, a3 = e1.y, a4 = e2.x;
            sw0a = a1 + 2.f * a2 + a3;  dw0a = a3 - a1;
            sw0b = a2 + 2.f * a3 + a4;  dw0b = a4 - a2;
        }
        {
            float2 e0 = *(const float2*)(p + PW + 2);
            float2 e1 = *(const float2*)(p + PW + 4);
            float2 e2 = *(const float2*)(p + PW + 6);
            float a1 = e0.y, a2 = e1.x, a3 = e1.y, a4 = e2.x;
            sw1a = a1 + 2.f * a2 + a3;  dw1a = a3 - a1;
            sw1b = a2 + 2.f * a3 + a4;  dw1b = a4 - a2;
            CC.x = a2; CC.y = a3;
        }
        {
            float2 e0 = *(const float2*)(p + 2 * PW + 2);
            float2 e1 = *(const float2*)(p + 2 * PW + 4);
            float2 e2 = *(const float2*)(p + 2 * PW + 6);
            float a1 = e0.y, a2 = e1.x, a3 = e1.y, a4 = e2.x;
            sw2a = a1 + 2.f * a2 + a3;  dw2a = a3 - a1;
            sw2b = a2 + 2.f * a3 + a4;  dw2b = a4 - a2;
        }
        P.x  = sw0a + 2.f * sw1a + sw2a;  P.y  = sw0b + 2.f * sw1b + sw2b;
        QW.x = dw0a + 2.f * dw1a + dw2a;  QW.y = dw0b + 2.f * dw1b + dw2b;
        QH.x = sw2a - sw0a;               QH.y = sw2b - sw0b;
    };

    float2 Pp, Pc, Pn, Wp, Wc, Wn, Hp, Hc, Hn, Cc, Cn, Cd;

    // prologue: planes z0-1 .. z0+3 into bufs 0..4
    loadPlane(true, z0 - 1, 0);
    loadPlane(true, z0 + 0, 1);
    loadPlane(true, z0 + 1, 2);
    loadPlane(true, z0 + 2, 3);
    loadPlane(true, z0 + 3, 4);
    cp_wait<3>();          // planes z0-1, z0 complete
    __syncthreads();
    stats(0, Pp, Wp, Hp, Cd);
    stats(1, Pc, Wc, Hc, Cc);

    #pragma unroll 4
    for (int t = 0; t < ZLEN; t++) {
        const int z = z0 + t;
        // prefetch plane z+4 into buf (t+5)&7 (held plane z-4, last read at iter t-5);
        // last needed plane is z0+ZLEN, so skip (empty group) when t+4 > ZLEN.
        loadPlane(t + 4 <= ZLEN, z + 4, (t + 5) & 7);
        cp_wait<3>();      // plane z+1 complete (up to 3 newer groups in flight)
        __syncthreads();

        stats((t + 2) & 7, Pn, Wn, Hn, Cn);

        float2 sx, sy, sz;
        sx.x = (Wp.x + 2.f * Wc.x + Wn.x) * 0.0625f;
        sx.y = (Wp.y + 2.f * Wc.y + Wn.y) * 0.0625f;
        sy.x = (Hp.x + 2.f * Hc.x + Hn.x) * 0.0625f;
        sy.y = (Hp.y + 2.f * Hc.y + Hn.y) * 0.0625f;
        sz.x = (Pn.x - Pp.x) * 0.0625f;
        sz.y = (Pn.y - Pp.y) * 0.0625f;

        const size_t o = (size_t)z * 4096 + line;
        __stcs((float2*)(out0 + o),                Cc);
        __stcs((float2*)(out0 + o + 16 * cstride), sx);
        __stcs((float2*)(out0 + o + 32 * cstride), sy);
        __stcs((float2*)(out0 + o + 48 * cstride), sz);

        Pp = Pc; Pc = Pn;
        Wp = Wc; Wc = Wn;
        Hp = Hc; Hc = Hn;
        Cc = Cn;
    }
}

extern "C" void kernel_launch(void* const* d_in, const int* in_sizes, int n_in,
                              void* d_out, int out_size) {
    const float* x = (const float*)d_in[0];
    // d_in[1] = kernels (4x3x3x3) — fixed separable stencils folded into the kernel.
    float* out = (float*)d_out;

    dim3 grid(64 / HT, 64, 64 / ZLEN);  // (8 H tiles, B*C=64, 4 z chunks) = 2048 blocks
    dim3 block(32, HT);                 // 256 threads
    perceive3d_kernel<<<grid, block>>>(x, out);
}